// round 1
// baseline (speedup 1.0000x reference)
#include <cuda_runtime.h>

#define N_NODES 100000
#define N_EDGES 1600000
#define ET      (N_EDGES + N_NODES)   // edges + self loops
#define N_GRAPHS 512
#define NEG_SLOPE 0.2f

// ---------------- scratch (static device globals; no allocs allowed) --------
__device__ float g_h1[N_NODES * 64];     // conv1 transformed features
__device__ float g_as1[N_NODES * 8];     // conv1 attention src scores
__device__ float g_ad1[N_NODES * 8];     // conv1 attention dst scores
__device__ float g_x2[N_NODES * 64];     // conv1 output (post ELU)
__device__ float g_h2[N_NODES * 128];    // conv2 transformed features
__device__ float g_as2[N_NODES];
__device__ float g_ad2[N_NODES];
__device__ int   g_deg[N_NODES];
__device__ int   g_rowptr[N_NODES + 1];
__device__ int   g_cursor[N_NODES];
__device__ int   g_csr[ET];              // src node per incoming edge, grouped by dst

// ---------------- init: zero degree hist, seed output with bg ---------------
__global__ void k_init(float* __restrict__ out, const float* __restrict__ bg) {
    int t = blockIdx.x * blockDim.x + threadIdx.x;
    if (t < N_NODES) g_deg[t] = 0;
    if (t < N_GRAPHS) out[t] = bg[0];
}

// ---------------- CSR build -------------------------------------------------
__global__ void k_hist(const int* __restrict__ ei) {
    int t = blockIdx.x * blockDim.x + threadIdx.x;
    if (t >= ET) return;
    int dst = (t < N_EDGES) ? ei[N_EDGES + t] : (t - N_EDGES);
    atomicAdd(&g_deg[dst], 1);
}

// single-block exclusive scan of g_deg -> g_rowptr, g_cursor
__global__ void k_scan() {
    __shared__ int ws[32];
    __shared__ int s_carry;
    const int t = threadIdx.x;
    const int lane = t & 31, wid = t >> 5;
    if (t == 0) s_carry = 0;
    __syncthreads();
    for (int base = 0; base < N_NODES; base += 1024) {
        int idx = base + t;
        int v = (idx < N_NODES) ? g_deg[idx] : 0;
        int x = v;
        #pragma unroll
        for (int d = 1; d < 32; d <<= 1) {
            int y = __shfl_up_sync(0xffffffffu, x, d);
            if (lane >= d) x += y;
        }
        if (lane == 31) ws[wid] = x;
        __syncthreads();
        if (wid == 0) {
            int wv = ws[lane];
            #pragma unroll
            for (int d = 1; d < 32; d <<= 1) {
                int y = __shfl_up_sync(0xffffffffu, wv, d);
                if (lane >= d) wv += y;
            }
            ws[lane] = wv;
        }
        __syncthreads();
        int add = s_carry + (wid ? ws[wid - 1] : 0);
        int excl = add + x - v;
        if (idx < N_NODES) { g_rowptr[idx] = excl; g_cursor[idx] = excl; }
        __syncthreads();
        if (t == 0) s_carry += ws[31];
        __syncthreads();
    }
    if (t == 0) g_rowptr[N_NODES] = s_carry;
}

__global__ void k_scatter(const int* __restrict__ ei) {
    int t = blockIdx.x * blockDim.x + threadIdx.x;
    if (t >= ET) return;
    int src, dst;
    if (t < N_EDGES) { src = ei[t]; dst = ei[N_EDGES + t]; }
    else             { src = dst = t - N_EDGES; }
    int pos = atomicAdd(&g_cursor[dst], 1);
    g_csr[pos] = src;
}

// ---------------- GEMM1: h1[N,64] = x[N,75] @ W1[75,64] ---------------------
// 64x64 tile per 256-thread block, 4x4 microtile.
__global__ __launch_bounds__(256) void k_gemm1(const float* __restrict__ x,
                                               const float* __restrict__ W) {
    __shared__ float As[75 * 64];   // As[k][r] (A transposed)
    __shared__ float Bs[75 * 64];   // Bs[k][c]
    const int t = threadIdx.x;
    const int m0 = blockIdx.x * 64;
    for (int i = t; i < 75 * 64; i += 256) Bs[i] = W[i];
    for (int i = t; i < 64 * 75; i += 256) {
        int r = i / 75, k = i - r * 75;
        int gi = m0 + r;
        As[k * 64 + r] = (gi < N_NODES) ? x[gi * 75 + k] : 0.f;
    }
    __syncthreads();
    const int tx = t & 15, ty = t >> 4;
    const int r0 = ty * 4, c0 = tx * 4;
    float acc[4][4] = {};
    #pragma unroll 3
    for (int k = 0; k < 75; k++) {
        float4 av = *(const float4*)(As + k * 64 + r0);
        float4 bv = *(const float4*)(Bs + k * 64 + c0);
        float ar[4] = {av.x, av.y, av.z, av.w};
        float br[4] = {bv.x, bv.y, bv.z, bv.w};
        #pragma unroll
        for (int r = 0; r < 4; r++)
            #pragma unroll
            for (int c = 0; c < 4; c++) acc[r][c] += ar[r] * br[c];
    }
    #pragma unroll
    for (int r = 0; r < 4; r++) {
        int gi = m0 + r0 + r;
        if (gi < N_NODES)
            *(float4*)(g_h1 + gi * 64 + c0) =
                make_float4(acc[r][0], acc[r][1], acc[r][2], acc[r][3]);
    }
}

// ---------------- att1: per (node, head) dot of 8 channels ------------------
__global__ void k_att1(const float* __restrict__ att_src,
                       const float* __restrict__ att_dst) {
    int t = blockIdx.x * blockDim.x + threadIdx.x;
    if (t >= N_NODES * 8) return;
    int i = t >> 3, h = t & 7;
    const float4* hp = (const float4*)(g_h1 + i * 64 + h * 8);
    float4 p = hp[0], q = hp[1];
    const float4* sp = (const float4*)(att_src + h * 8);
    const float4* dp = (const float4*)(att_dst + h * 8);
    float4 s0 = sp[0], s1 = sp[1], d0 = dp[0], d1 = dp[1];
    g_as1[t] = p.x*s0.x + p.y*s0.y + p.z*s0.z + p.w*s0.w
             + q.x*s1.x + q.y*s1.y + q.z*s1.z + q.w*s1.w;
    g_ad1[t] = p.x*d0.x + p.y*d0.y + p.z*d0.z + p.w*d0.w
             + q.x*d1.x + q.y*d1.y + q.z*d1.z + q.w*d1.w;
}

// ---------------- conv1 aggregation: warp per node --------------------------
// lane l covers channels {2l, 2l+1}, head = l>>2. Unnormalized softmax
// (exp without max-shift -- mathematically identical alpha), local denom.
__global__ void k_edge1(const float* __restrict__ bias1) {
    int w = (blockIdx.x * blockDim.x + threadIdx.x) >> 5;
    if (w >= N_NODES) return;
    int lane = threadIdx.x & 31;
    int hl = lane >> 2;
    int co = lane * 2;
    float adst = g_ad1[w * 8 + hl];
    float accx = 0.f, accy = 0.f, den = 0.f;
    int e0 = g_rowptr[w], e1 = g_rowptr[w + 1];
    for (int e = e0; e < e1; e++) {
        int s = g_csr[e];
        float ea = g_as1[s * 8 + hl] + adst;
        ea = (ea > 0.f) ? ea : NEG_SLOPE * ea;
        float ee = __expf(ea);
        float2 hv = *(const float2*)(g_h1 + s * 64 + co);
        accx += ee * hv.x;
        accy += ee * hv.y;
        den  += ee;
    }
    float inv = 1.f / den;           // den identical across the 4 lanes of a head
    float2 b = *(const float2*)(bias1 + co);
    float vx = accx * inv + b.x;
    float vy = accy * inv + b.y;
    vx = (vx > 0.f) ? vx : (__expf(vx) - 1.f);   // ELU
    vy = (vy > 0.f) ? vy : (__expf(vy) - 1.f);
    *(float2*)(g_x2 + w * 64 + co) = make_float2(vx, vy);
}

// ---------------- GEMM2: h2[N,128] = x2[N,64] @ W2[64,128] ------------------
// 64x128 tile per 256-thread block, 4x8 microtile. 48KB static smem.
__global__ __launch_bounds__(256) void k_gemm2(const float* __restrict__ W) {
    __shared__ float As[64 * 64];    // As[k][r]
    __shared__ float Bs[64 * 128];   // Bs[k][c]
    const int t = threadIdx.x;
    const int m0 = blockIdx.x * 64;
    for (int i = t; i < 64 * 128; i += 256) Bs[i] = W[i];
    for (int i = t; i < 64 * 64; i += 256) {
        int r = i >> 6, k = i & 63;
        int gi = m0 + r;
        As[k * 64 + r] = (gi < N_NODES) ? g_x2[gi * 64 + k] : 0.f;
    }
    __syncthreads();
    const int tx = t & 15, ty = t >> 4;
    const int r0 = ty * 4, c0 = tx * 8;
    float acc[4][8] = {};
    #pragma unroll 2
    for (int k = 0; k < 64; k++) {
        float4 av = *(const float4*)(As + k * 64 + r0);
        float4 b0 = *(const float4*)(Bs + k * 128 + c0);
        float4 b1 = *(const float4*)(Bs + k * 128 + c0 + 4);
        float ar[4] = {av.x, av.y, av.z, av.w};
        float br[8] = {b0.x, b0.y, b0.z, b0.w, b1.x, b1.y, b1.z, b1.w};
        #pragma unroll
        for (int r = 0; r < 4; r++)
            #pragma unroll
            for (int c = 0; c < 8; c++) acc[r][c] += ar[r] * br[c];
    }
    #pragma unroll
    for (int r = 0; r < 4; r++) {
        int gi = m0 + r0 + r;
        if (gi < N_NODES) {
            *(float4*)(g_h2 + gi * 128 + c0) =
                make_float4(acc[r][0], acc[r][1], acc[r][2], acc[r][3]);
            *(float4*)(g_h2 + gi * 128 + c0 + 4) =
                make_float4(acc[r][4], acc[r][5], acc[r][6], acc[r][7]);
        }
    }
}

// ---------------- att2: warp per node, dot over 128 channels ----------------
__global__ void k_att2(const float* __restrict__ att_src,
                       const float* __restrict__ att_dst) {
    int w = (blockIdx.x * blockDim.x + threadIdx.x) >> 5;
    if (w >= N_NODES) return;
    int lane = threadIdx.x & 31;
    float4 h = *(const float4*)(g_h2 + w * 128 + lane * 4);
    float4 s = *(const float4*)(att_src + lane * 4);
    float4 d = *(const float4*)(att_dst + lane * 4);
    float ds = h.x*s.x + h.y*s.y + h.z*s.z + h.w*s.w;
    float dd = h.x*d.x + h.y*d.y + h.z*d.z + h.w*d.w;
    #pragma unroll
    for (int o = 16; o > 0; o >>= 1) {
        ds += __shfl_down_sync(0xffffffffu, ds, o);
        dd += __shfl_down_sync(0xffffffffu, dd, o);
    }
    if (lane == 0) { g_as2[w] = ds; g_ad2[w] = dd; }
}

// ---------------- conv2 aggregation + pool + final linear, fully fused ------
// warp per node: lane covers 4 channels. Never materializes x4: folds
// /denom + bias2, dot with Wg, and atomicAdd into the 512-graph output.
__global__ void k_edge2(const float* __restrict__ bias2,
                        const float* __restrict__ Wg,
                        const int* __restrict__ batch,
                        float* __restrict__ out) {
    int w = (blockIdx.x * blockDim.x + threadIdx.x) >> 5;
    if (w >= N_NODES) return;
    int lane = threadIdx.x & 31;
    int co = lane * 4;
    float adst = g_ad2[w];
    float ax = 0.f, ay = 0.f, az = 0.f, aw = 0.f, den = 0.f;
    int e0 = g_rowptr[w], e1 = g_rowptr[w + 1];
    for (int e = e0; e < e1; e++) {
        int s = g_csr[e];
        float ea = g_as2[s] + adst;
        ea = (ea > 0.f) ? ea : NEG_SLOPE * ea;
        float ee = __expf(ea);
        float4 hv = *(const float4*)(g_h2 + s * 128 + co);
        ax += ee * hv.x; ay += ee * hv.y; az += ee * hv.z; aw += ee * hv.w;
        den += ee;
    }
    float inv = 1.f / den;                     // identical across all lanes
    float4 b = *(const float4*)(bias2 + co);
    float4 g = *(const float4*)(Wg + co);
    float part = (ax * inv + b.x) * g.x + (ay * inv + b.y) * g.y
               + (az * inv + b.z) * g.z + (aw * inv + b.w) * g.w;
    #pragma unroll
    for (int o = 16; o > 0; o >>= 1)
        part += __shfl_down_sync(0xffffffffu, part, o);
    if (lane == 0) atomicAdd(out + batch[w], part);
}

// ---------------- launch ----------------------------------------------------
extern "C" void kernel_launch(void* const* d_in, const int* in_sizes, int n_in,
                              void* d_out, int out_size) {
    const float* x        = (const float*)d_in[0];
    const int*   ei       = (const int*)  d_in[1];
    const int*   batch    = (const int*)  d_in[2];
    const float* W1       = (const float*)d_in[3];
    const float* att_src1 = (const float*)d_in[4];
    const float* att_dst1 = (const float*)d_in[5];
    const float* bias1    = (const float*)d_in[6];
    const float* W2       = (const float*)d_in[7];
    const float* att_src2 = (const float*)d_in[8];
    const float* att_dst2 = (const float*)d_in[9];
    const float* bias2    = (const float*)d_in[10];
    const float* Wg       = (const float*)d_in[11];
    const float* bg       = (const float*)d_in[12];
    float* out = (float*)d_out;

    k_init<<<(N_NODES + 255) / 256, 256>>>(out, bg);
    k_hist<<<(ET + 255) / 256, 256>>>(ei);
    k_scan<<<1, 1024>>>();
    k_scatter<<<(ET + 255) / 256, 256>>>(ei);

    k_gemm1<<<(N_NODES + 63) / 64, 256>>>(x, W1);
    k_att1<<<(N_NODES * 8 + 255) / 256, 256>>>(att_src1, att_dst1);
    k_edge1<<<(N_NODES * 32 + 255) / 256, 256>>>(bias1);

    k_gemm2<<<(N_NODES + 63) / 64, 256>>>(W2);
    k_att2<<<(N_NODES * 32 + 255) / 256, 256>>>(att_src2, att_dst2);
    k_edge2<<<(N_NODES * 32 + 255) / 256, 256>>>(bias2, Wg, batch, out);
}

// round 2
// speedup vs baseline: 1.3980x; 1.3980x over previous
#include <cuda_runtime.h>

#define N_NODES 100000
#define N_EDGES 1600000
#define ET      (N_EDGES + N_NODES)   // edges + self loops
#define N_GRAPHS 512
#define NEG_SLOPE 0.2f

// ---------------- scratch (static device globals; no allocs allowed) --------
__device__ float  g_h1[N_NODES * 64];     // conv1 transformed features
__device__ float  g_as1[N_NODES * 8];     // conv1 attention src scores
__device__ float  g_ad1[N_NODES * 8];     // conv1 attention dst scores
__device__ float2 g_ap2[N_NODES];         // (as2, p=h2.Wg) per node, packed
__device__ float  g_ad2[N_NODES];
__device__ float  g_M3[64 * 3];           // W2 @ [att_src2^T | att_dst2^T | Wg]
__device__ float  g_c2;                   // bias2 . Wg
__device__ int    g_deg[N_NODES];
__device__ int    g_rowptr[N_NODES + 1];
__device__ int    g_cursor[N_NODES];
__device__ int    g_csr[ET];              // src node per incoming edge, grouped by dst

// ---------------- init: zero degree hist, seed output with bg ---------------
__global__ void k_init(float* __restrict__ out, const float* __restrict__ bg) {
    int t = blockIdx.x * blockDim.x + threadIdx.x;
    if (t < N_NODES) g_deg[t] = 0;
    if (t < N_GRAPHS) out[t] = bg[0];
}

// ---------------- CSR build -------------------------------------------------
__global__ void k_hist(const int* __restrict__ ei) {
    int t = blockIdx.x * blockDim.x + threadIdx.x;
    if (t >= ET) return;
    int dst = (t < N_EDGES) ? ei[N_EDGES + t] : (t - N_EDGES);
    atomicAdd(&g_deg[dst], 1);
}

// single-block exclusive scan of g_deg -> g_rowptr, g_cursor
__global__ void k_scan() {
    __shared__ int ws[32];
    __shared__ int s_carry;
    const int t = threadIdx.x;
    const int lane = t & 31, wid = t >> 5;
    if (t == 0) s_carry = 0;
    __syncthreads();
    for (int base = 0; base < N_NODES; base += 1024) {
        int idx = base + t;
        int v = (idx < N_NODES) ? g_deg[idx] : 0;
        int x = v;
        #pragma unroll
        for (int d = 1; d < 32; d <<= 1) {
            int y = __shfl_up_sync(0xffffffffu, x, d);
            if (lane >= d) x += y;
        }
        if (lane == 31) ws[wid] = x;
        __syncthreads();
        if (wid == 0) {
            int wv = ws[lane];
            #pragma unroll
            for (int d = 1; d < 32; d <<= 1) {
                int y = __shfl_up_sync(0xffffffffu, wv, d);
                if (lane >= d) wv += y;
            }
            ws[lane] = wv;
        }
        __syncthreads();
        int add = s_carry + (wid ? ws[wid - 1] : 0);
        int excl = add + x - v;
        if (idx < N_NODES) { g_rowptr[idx] = excl; g_cursor[idx] = excl; }
        __syncthreads();
        if (t == 0) s_carry += ws[31];
        __syncthreads();
    }
    if (t == 0) g_rowptr[N_NODES] = s_carry;
}

__global__ void k_scatter(const int* __restrict__ ei) {
    int t = blockIdx.x * blockDim.x + threadIdx.x;
    if (t >= ET) return;
    int src, dst;
    if (t < N_EDGES) { src = ei[t]; dst = ei[N_EDGES + t]; }
    else             { src = dst = t - N_EDGES; }
    int pos = atomicAdd(&g_cursor[dst], 1);
    g_csr[pos] = src;
}

// ---------------- prep: M3 = W2 @ [att_src2^T|att_dst2^T|Wg], c2 = bias2.Wg -
__global__ void k_prep(const float* __restrict__ W2,
                       const float* __restrict__ as2v,
                       const float* __restrict__ ad2v,
                       const float* __restrict__ Wg,
                       const float* __restrict__ bias2) {
    int t = threadIdx.x;
    if (t < 192) {
        int c = t & 63, j = t >> 6;
        const float* v = (j == 0) ? as2v : (j == 1) ? ad2v : Wg;
        float s = 0.f;
        #pragma unroll 4
        for (int o = 0; o < 128; o++) s += W2[c * 128 + o] * v[o];
        g_M3[c * 3 + j] = s;
    } else if (t < 224) {
        int lane = t - 192;
        float s = 0.f;
        for (int o = lane; o < 128; o += 32) s += bias2[o] * Wg[o];
        #pragma unroll
        for (int o = 16; o; o >>= 1) s += __shfl_xor_sync(0xffffffffu, s, o);
        if (lane == 0) g_c2 = s;
    }
}

// ---------------- GEMM1: h1[N,64] = x[N,75] @ W1[75,64] ---------------------
__global__ __launch_bounds__(256) void k_gemm1(const float* __restrict__ x,
                                               const float* __restrict__ W) {
    __shared__ float As[75 * 64];   // As[k][r] (A transposed)
    __shared__ float Bs[75 * 64];   // Bs[k][c]
    const int t = threadIdx.x;
    const int m0 = blockIdx.x * 64;
    for (int i = t; i < 75 * 64; i += 256) Bs[i] = W[i];
    for (int i = t; i < 64 * 75; i += 256) {
        int r = i / 75, k = i - r * 75;
        int gi = m0 + r;
        As[k * 64 + r] = (gi < N_NODES) ? x[gi * 75 + k] : 0.f;
    }
    __syncthreads();
    const int tx = t & 15, ty = t >> 4;
    const int r0 = ty * 4, c0 = tx * 4;
    float acc[4][4] = {};
    #pragma unroll 3
    for (int k = 0; k < 75; k++) {
        float4 av = *(const float4*)(As + k * 64 + r0);
        float4 bv = *(const float4*)(Bs + k * 64 + c0);
        float ar[4] = {av.x, av.y, av.z, av.w};
        float br[4] = {bv.x, bv.y, bv.z, bv.w};
        #pragma unroll
        for (int r = 0; r < 4; r++)
            #pragma unroll
            for (int c = 0; c < 4; c++) acc[r][c] += ar[r] * br[c];
    }
    #pragma unroll
    for (int r = 0; r < 4; r++) {
        int gi = m0 + r0 + r;
        if (gi < N_NODES)
            *(float4*)(g_h1 + gi * 64 + c0) =
                make_float4(acc[r][0], acc[r][1], acc[r][2], acc[r][3]);
    }
}

// ---------------- att1: per (node, head) dot of 8 channels ------------------
__global__ void k_att1(const float* __restrict__ att_src,
                       const float* __restrict__ att_dst) {
    int t = blockIdx.x * blockDim.x + threadIdx.x;
    if (t >= N_NODES * 8) return;
    int i = t >> 3, h = t & 7;
    const float4* hp = (const float4*)(g_h1 + i * 64 + h * 8);
    float4 p = hp[0], q = hp[1];
    const float4* sp = (const float4*)(att_src + h * 8);
    const float4* dp = (const float4*)(att_dst + h * 8);
    float4 s0 = sp[0], s1 = sp[1], d0 = dp[0], d1 = dp[1];
    g_as1[t] = p.x*s0.x + p.y*s0.y + p.z*s0.z + p.w*s0.w
             + q.x*s1.x + q.y*s1.y + q.z*s1.z + q.w*s1.w;
    g_ad1[t] = p.x*d0.x + p.y*d0.y + p.z*d0.z + p.w*d0.w
             + q.x*d1.x + q.y*d1.y + q.z*d1.z + q.w*d1.w;
}

// ---------------- conv1 aggregation + conv2-score projection, fused ---------
// warp per node: lane l covers channels {2l, 2l+1}, head = l>>2.
// Epilogue: x2 (registers only) -> [as2, ad2, p] = x2 . M3 columns.
__global__ void k_edge1(const float* __restrict__ bias1) {
    int w = (blockIdx.x * blockDim.x + threadIdx.x) >> 5;
    if (w >= N_NODES) return;
    int lane = threadIdx.x & 31;
    int hl = lane >> 2;
    int co = lane * 2;
    float adst = g_ad1[w * 8 + hl];
    float accx = 0.f, accy = 0.f, den = 0.f;
    int e0 = g_rowptr[w], e1 = g_rowptr[w + 1];
    for (int e = e0; e < e1; e++) {
        int s = g_csr[e];
        float ea = g_as1[s * 8 + hl] + adst;
        ea = (ea > 0.f) ? ea : NEG_SLOPE * ea;
        float ee = __expf(ea);
        float2 hv = *(const float2*)(g_h1 + s * 64 + co);
        accx += ee * hv.x;
        accy += ee * hv.y;
        den  += ee;
    }
    float inv = 1.f / den;           // den identical across the 4 lanes of a head
    float2 b = *(const float2*)(bias1 + co);
    float vx = accx * inv + b.x;
    float vy = accy * inv + b.y;
    vx = (vx > 0.f) ? vx : (__expf(vx) - 1.f);   // ELU
    vy = (vy > 0.f) ? vy : (__expf(vy) - 1.f);
    // project x2 row onto the 3 fused conv2 vectors
    float s0 = vx * g_M3[co * 3 + 0] + vy * g_M3[co * 3 + 3];
    float s1 = vx * g_M3[co * 3 + 1] + vy * g_M3[co * 3 + 4];
    float s2 = vx * g_M3[co * 3 + 2] + vy * g_M3[co * 3 + 5];
    #pragma unroll
    for (int o = 16; o; o >>= 1) {
        s0 += __shfl_xor_sync(0xffffffffu, s0, o);
        s1 += __shfl_xor_sync(0xffffffffu, s1, o);
        s2 += __shfl_xor_sync(0xffffffffu, s2, o);
    }
    if (lane == 0) {
        g_ap2[w] = make_float2(s0, s2);   // (as2, p)
        g_ad2[w] = s1;
    }
}

// ---------------- conv2 aggregation + pool + final linear, scalarized -------
// warp per node, lanes stride edges. 12 B/edge total traffic.
__global__ void k_edge2(const int* __restrict__ batch,
                        float* __restrict__ out) {
    int w = (blockIdx.x * blockDim.x + threadIdx.x) >> 5;
    if (w >= N_NODES) return;
    int lane = threadIdx.x & 31;
    float adst = g_ad2[w];
    float num = 0.f, den = 0.f;
    int e0 = g_rowptr[w], e1 = g_rowptr[w + 1];
    for (int e = e0 + lane; e < e1; e += 32) {
        int s = g_csr[e];
        float2 ap = g_ap2[s];
        float ea = ap.x + adst;
        ea = (ea > 0.f) ? ea : NEG_SLOPE * ea;
        float ee = __expf(ea);
        num += ee * ap.y;
        den += ee;
    }
    #pragma unroll
    for (int o = 16; o; o >>= 1) {
        num += __shfl_xor_sync(0xffffffffu, num, o);
        den += __shfl_xor_sync(0xffffffffu, den, o);
    }
    if (lane == 0) atomicAdd(out + batch[w], num / den + g_c2);
}

// ---------------- launch ----------------------------------------------------
extern "C" void kernel_launch(void* const* d_in, const int* in_sizes, int n_in,
                              void* d_out, int out_size) {
    const float* x        = (const float*)d_in[0];
    const int*   ei       = (const int*)  d_in[1];
    const int*   batch    = (const int*)  d_in[2];
    const float* W1       = (const float*)d_in[3];
    const float* att_src1 = (const float*)d_in[4];
    const float* att_dst1 = (const float*)d_in[5];
    const float* bias1    = (const float*)d_in[6];
    const float* W2       = (const float*)d_in[7];
    const float* att_src2 = (const float*)d_in[8];
    const float* att_dst2 = (const float*)d_in[9];
    const float* bias2    = (const float*)d_in[10];
    const float* Wg       = (const float*)d_in[11];
    const float* bg       = (const float*)d_in[12];
    float* out = (float*)d_out;

    k_init<<<(N_NODES + 255) / 256, 256>>>(out, bg);
    k_hist<<<(ET + 255) / 256, 256>>>(ei);
    k_scan<<<1, 1024>>>();
    k_scatter<<<(ET + 255) / 256, 256>>>(ei);

    k_prep<<<1, 256>>>(W2, att_src2, att_dst2, Wg, bias2);
    k_gemm1<<<(N_NODES + 63) / 64, 256>>>(x, W1);
    k_att1<<<(N_NODES * 8 + 255) / 256, 256>>>(att_src1, att_dst1);
    k_edge1<<<(N_NODES * 32 + 255) / 256, 256>>>(bias1);
    k_edge2<<<(N_NODES * 32 + 255) / 256, 256>>>(batch, out);
}

// round 3
// speedup vs baseline: 1.8746x; 1.3409x over previous
#include <cuda_runtime.h>

#define N_NODES 100000
#define N_EDGES 1600000
#define ET      (N_EDGES + N_NODES)   // edges + self loops
#define N_GRAPHS 512
#define NEG_SLOPE 0.2f
#define N4 (N_NODES / 4)              // 25000, exact

// ---------------- scratch (static device globals; no allocs allowed) --------
__device__ __align__(16) float  g_h1[N_NODES * 64];   // conv1 transformed features
__device__ __align__(16) float  g_as1[N_NODES * 8];   // conv1 attention src scores
__device__ __align__(16) float  g_ad1[N_NODES * 8];   // conv1 attention dst scores
__device__ float2 g_ap2[N_NODES];         // (as2, p=h2.Wg) per node, packed
__device__ float  g_ad2[N_NODES];
__device__ float  g_M3[64 * 3];           // W2 @ [att_src2^T | att_dst2^T | Wg]
__device__ float  g_c2;                   // bias2 . Wg
__device__ __align__(16) int g_deg[N_NODES];
__device__ __align__(16) int g_rowptr[N_NODES + 4];
__device__ __align__(16) int g_cursor[N_NODES];
__device__ int    g_csr[ET];              // src node per incoming edge, grouped by dst

// ---------------- init (deg=1 for self loop, out=bg) + prep (M3, c2) --------
__global__ void k_init_prep(float* __restrict__ out, const float* __restrict__ bg,
                            const float* __restrict__ W2,
                            const float* __restrict__ as2v,
                            const float* __restrict__ ad2v,
                            const float* __restrict__ Wg,
                            const float* __restrict__ bias2) {
    if (blockIdx.x == 0) {
        int t = threadIdx.x;
        if (t < 192) {
            int c = t & 63, j = t >> 6;
            const float* v = (j == 0) ? as2v : (j == 1) ? ad2v : Wg;
            float s = 0.f;
            #pragma unroll 4
            for (int o = 0; o < 128; o++) s += W2[c * 128 + o] * v[o];
            g_M3[c * 3 + j] = s;
        } else if (t < 224) {
            int lane = t - 192;
            float s = 0.f;
            for (int o = lane; o < 128; o += 32) s += bias2[o] * Wg[o];
            #pragma unroll
            for (int o = 16; o; o >>= 1) s += __shfl_xor_sync(0xffffffffu, s, o);
            if (lane == 0) g_c2 = s;
        }
        return;
    }
    int t = (blockIdx.x - 1) * blockDim.x + threadIdx.x;
    if (t < N_NODES) g_deg[t] = 1;          // self-loop pre-counted
    if (t < N_GRAPHS) out[t] = bg[0];
}

// ---------------- CSR build -------------------------------------------------
__global__ void k_hist(const int* __restrict__ ei) {
    int t = blockIdx.x * blockDim.x + threadIdx.x;
    if (t >= N_EDGES) return;
    atomicAdd(&g_deg[ei[N_EDGES + t]], 1);
}

// single-block exclusive scan of g_deg -> g_rowptr, g_cursor (int4-wide)
__global__ void k_scan() {
    __shared__ int ws[32];
    __shared__ int s_carry;
    const int t = threadIdx.x;
    const int lane = t & 31, wid = t >> 5;
    if (t == 0) s_carry = 0;
    __syncthreads();
    const int4* deg4 = (const int4*)g_deg;
    for (int base = 0; base < N4; base += 1024) {
        int idx = base + t;
        int4 v = (idx < N4) ? deg4[idx] : make_int4(0, 0, 0, 0);
        int s1 = v.x + v.y, s2 = s1 + v.z, s3 = s2 + v.w;
        int x = s3;
        #pragma unroll
        for (int d = 1; d < 32; d <<= 1) {
            int y = __shfl_up_sync(0xffffffffu, x, d);
            if (lane >= d) x += y;
        }
        if (lane == 31) ws[wid] = x;
        __syncthreads();
        if (wid == 0) {
            int wv = ws[lane];
            #pragma unroll
            for (int d = 1; d < 32; d <<= 1) {
                int y = __shfl_up_sync(0xffffffffu, wv, d);
                if (lane >= d) wv += y;
            }
            ws[lane] = wv;
        }
        __syncthreads();
        int add = s_carry + (wid ? ws[wid - 1] : 0);
        int e0 = add + x - s3;     // exclusive prefix before this thread's 4
        if (idx < N4) {
            int4 r = make_int4(e0, e0 + v.x, e0 + s1, e0 + s2);
            ((int4*)g_rowptr)[idx] = r;
            ((int4*)g_cursor)[idx] = r;
        }
        __syncthreads();
        if (t == 0) s_carry += ws[31];
        __syncthreads();
    }
    if (t == 0) g_rowptr[N_NODES] = s_carry;
}

__global__ void k_scatter(const int* __restrict__ ei) {
    int t = blockIdx.x * blockDim.x + threadIdx.x;
    if (t >= ET) return;
    int src, dst;
    if (t < N_EDGES) { src = ei[t]; dst = ei[N_EDGES + t]; }
    else             { src = dst = t - N_EDGES; }
    int pos = atomicAdd(&g_cursor[dst], 1);
    g_csr[pos] = src;
}

// ---------------- GEMM1 + att1 fused: h1 = x @ W1, a_src/a_dst dots ---------
__global__ __launch_bounds__(256) void k_gemm1(const float* __restrict__ x,
                                               const float* __restrict__ W,
                                               const float* __restrict__ att_src,
                                               const float* __restrict__ att_dst) {
    __shared__ float As[75 * 64];   // As[k][r] (A transposed)
    __shared__ float Bs[75 * 64];   // Bs[k][c]
    const int t = threadIdx.x;
    const int m0 = blockIdx.x * 64;
    for (int i = t; i < 75 * 64; i += 256) Bs[i] = W[i];
    for (int i = t; i < 64 * 75; i += 256) {
        int r = i / 75, k = i - r * 75;
        int gi = m0 + r;
        As[k * 64 + r] = (gi < N_NODES) ? x[gi * 75 + k] : 0.f;
    }
    __syncthreads();
    const int tx = t & 15, ty = t >> 4;
    const int r0 = ty * 4, c0 = tx * 4;
    float acc[4][4] = {};
    #pragma unroll 3
    for (int k = 0; k < 75; k++) {
        float4 av = *(const float4*)(As + k * 64 + r0);
        float4 bv = *(const float4*)(Bs + k * 64 + c0);
        float ar[4] = {av.x, av.y, av.z, av.w};
        float br[4] = {bv.x, bv.y, bv.z, bv.w};
        #pragma unroll
        for (int r = 0; r < 4; r++)
            #pragma unroll
            for (int c = 0; c < 4; c++) acc[r][c] += ar[r] * br[c];
    }
    // att1 epilogue: head h = tx>>1; thread pair (tx, tx^1) spans its 8 chans
    const int h = tx >> 1, half = tx & 1;
    float4 sv = *(const float4*)(att_src + h * 8 + half * 4);
    float4 dv = *(const float4*)(att_dst + h * 8 + half * 4);
    #pragma unroll
    for (int r = 0; r < 4; r++) {
        int gi = m0 + r0 + r;
        float ps = acc[r][0]*sv.x + acc[r][1]*sv.y + acc[r][2]*sv.z + acc[r][3]*sv.w;
        float pd = acc[r][0]*dv.x + acc[r][1]*dv.y + acc[r][2]*dv.z + acc[r][3]*dv.w;
        ps += __shfl_xor_sync(0xffffffffu, ps, 1);
        pd += __shfl_xor_sync(0xffffffffu, pd, 1);
        if (gi < N_NODES) {
            *(float4*)(g_h1 + gi * 64 + c0) =
                make_float4(acc[r][0], acc[r][1], acc[r][2], acc[r][3]);
            if (half == 0) { g_as1[gi * 8 + h] = ps; g_ad1[gi * 8 + h] = pd; }
        }
    }
}

// ---------------- conv1 aggregation + conv2-score projection, fused ---------
// 16-lane group per node (2 nodes/warp): lane l covers 4 channels (float4),
// head = l>>1. Epilogue: x2 in registers -> [as2, ad2, p] projections.
__global__ void k_edge1(const float* __restrict__ bias1) {
    int g = (blockIdx.x * blockDim.x + threadIdx.x) >> 4;   // group id
    if (g >= N_NODES) return;
    int l = threadIdx.x & 15;
    int hl = l >> 1;
    int co = l * 4;
    int w = g;
    float adst = g_ad1[w * 8 + hl];
    float ax = 0.f, ay = 0.f, az = 0.f, aw = 0.f, den = 0.f;
    int e0 = g_rowptr[w], e1 = g_rowptr[w + 1];
    for (int e = e0; e < e1; e++) {
        int s = g_csr[e];
        float ea = g_as1[s * 8 + hl] + adst;
        ea = (ea > 0.f) ? ea : NEG_SLOPE * ea;
        float ee = __expf(ea);
        float4 hv = *(const float4*)(g_h1 + s * 64 + co);
        ax += ee * hv.x; ay += ee * hv.y; az += ee * hv.z; aw += ee * hv.w;
        den += ee;
    }
    float inv = 1.f / den;          // identical across the 2 lanes of a head
    float4 b = *(const float4*)(bias1 + co);
    float vx = ax * inv + b.x;
    float vy = ay * inv + b.y;
    float vz = az * inv + b.z;
    float vw = aw * inv + b.w;
    vx = (vx > 0.f) ? vx : (__expf(vx) - 1.f);   // ELU
    vy = (vy > 0.f) ? vy : (__expf(vy) - 1.f);
    vz = (vz > 0.f) ? vz : (__expf(vz) - 1.f);
    vw = (vw > 0.f) ? vw : (__expf(vw) - 1.f);
    // project x2 row onto the 3 fused conv2 vectors
    float s0 = vx*g_M3[co*3+0] + vy*g_M3[co*3+3] + vz*g_M3[co*3+6] + vw*g_M3[co*3+9];
    float s1 = vx*g_M3[co*3+1] + vy*g_M3[co*3+4] + vz*g_M3[co*3+7] + vw*g_M3[co*3+10];
    float s2 = vx*g_M3[co*3+2] + vy*g_M3[co*3+5] + vz*g_M3[co*3+8] + vw*g_M3[co*3+11];
    #pragma unroll
    for (int o = 8; o; o >>= 1) {    // group-local reduce (offsets < 16)
        s0 += __shfl_xor_sync(0xffffffffu, s0, o);
        s1 += __shfl_xor_sync(0xffffffffu, s1, o);
        s2 += __shfl_xor_sync(0xffffffffu, s2, o);
    }
    if (l == 0) {
        g_ap2[w] = make_float2(s0, s2);   // (as2, p)
        g_ad2[w] = s1;
    }
}

// ---------------- conv2 aggregation + pool + final linear, scalarized -------
// 8-lane group per node, lanes stride edges. 12 B/edge total traffic.
__global__ void k_edge2(const int* __restrict__ batch,
                        float* __restrict__ out) {
    int w = (blockIdx.x * blockDim.x + threadIdx.x) >> 3;
    if (w >= N_NODES) return;
    int l = threadIdx.x & 7;
    float adst = g_ad2[w];
    float num = 0.f, den = 0.f;
    int e0 = g_rowptr[w], e1 = g_rowptr[w + 1];
    for (int e = e0 + l; e < e1; e += 8) {
        int s = g_csr[e];
        float2 ap = g_ap2[s];
        float ea = ap.x + adst;
        ea = (ea > 0.f) ? ea : NEG_SLOPE * ea;
        float ee = __expf(ea);
        num += ee * ap.y;
        den += ee;
    }
    #pragma unroll
    for (int o = 4; o; o >>= 1) {    // group-local reduce (offsets < 8)
        num += __shfl_xor_sync(0xffffffffu, num, o);
        den += __shfl_xor_sync(0xffffffffu, den, o);
    }
    if (l == 0) atomicAdd(out + batch[w], num / den + g_c2);
}

// ---------------- launch ----------------------------------------------------
extern "C" void kernel_launch(void* const* d_in, const int* in_sizes, int n_in,
                              void* d_out, int out_size) {
    const float* x        = (const float*)d_in[0];
    const int*   ei       = (const int*)  d_in[1];
    const int*   batch    = (const int*)  d_in[2];
    const float* W1       = (const float*)d_in[3];
    const float* att_src1 = (const float*)d_in[4];
    const float* att_dst1 = (const float*)d_in[5];
    const float* bias1    = (const float*)d_in[6];
    const float* W2       = (const float*)d_in[7];
    const float* att_src2 = (const float*)d_in[8];
    const float* att_dst2 = (const float*)d_in[9];
    const float* bias2    = (const float*)d_in[10];
    const float* Wg       = (const float*)d_in[11];
    const float* bg       = (const float*)d_in[12];
    float* out = (float*)d_out;

    k_init_prep<<<1 + (N_NODES + 255) / 256, 256>>>(out, bg, W2, att_src2,
                                                    att_dst2, Wg, bias2);
    k_hist<<<(N_EDGES + 255) / 256, 256>>>(ei);
    k_scan<<<1, 1024>>>();
    k_scatter<<<(ET + 255) / 256, 256>>>(ei);

    k_gemm1<<<(N_NODES + 63) / 64, 256>>>(x, W1, att_src1, att_dst1);
    k_edge1<<<(N_NODES * 16 + 255) / 256, 256>>>(bias1);
    k_edge2<<<(N_NODES * 8 + 255) / 256, 256>>>(batch, out);
}